// round 7
// baseline (speedup 1.0000x reference)
#include <cuda_runtime.h>
#include <math.h>

#define BB 8
#define CC 256
#define TT 16
#define HWN 1024
#define CR 16

// ---------------- scratch (device globals; no allocation) -------------------
__device__ float g_hid_part[4 * BB * CR * HWN];  // partial hidden [q][b][r][hw] (2MB)
__device__ float g_tpp[BB * TT * 32 * CC];       // tp partials [b][t][tile][c] (4MB)
__device__ float g_cpp[BB * 32 * CC];            // cp partials [b][tile][c] (256KB)
__device__ float g_cp[BB * CC];                  // channel pooled mean
__device__ float g_comb[BB * CC * TT];           // temporal_att * channel_att
__device__ float g_att[BB * CC * HWN];           // spatial attention (8MB)

__device__ __forceinline__ float sigmoidf(float a) {
    return 1.0f / (1.0f + __expf(-a));
}

// ---------------- K1: stream x once -> hid partials + tp/cp partials ---------
// grid = BB * 32tiles * 4csplits = 1024 blocks, 256 threads, 16KB smem.
__global__ void __launch_bounds__(256) pool_hid_kernel(const float* __restrict__ x,
                                                       const float* __restrict__ ws1) {
    __shared__ float w1s[CR * 64];    // [r][c_local]
    __shared__ float sp_s[64 * 32];   // [c_local][hw_l]
    __shared__ float tp_s[TT * 64];   // [t][c_local]

    const int bx   = blockIdx.x;
    const int q    = bx & 3;
    const int tile = (bx >> 2) & 31;
    const int b    = bx >> 7;
    const int tid  = threadIdx.x;

    for (int i = tid; i < CR * 64; i += 256)
        w1s[i] = ws1[(i >> 6) * CC + q * 64 + (i & 63)];

    const int f4  = tid & 7;
    const int cl2 = tid >> 3;
    const float4* xb = (const float4*)x;

#pragma unroll
    for (int i = 0; i < 2; i++) {
        const int c_local = cl2 + 32 * i;
        const int c = q * 64 + c_local;
        const size_t rowbase = (size_t)(b * CC + c) * TT * (HWN / 4) + tile * 8 + f4;
        float4 sp = make_float4(0.f, 0.f, 0.f, 0.f);
        float ts[TT];
#pragma unroll
        for (int t = 0; t < TT; t++) {
            float4 v = xb[rowbase + t * (HWN / 4)];
            sp.x += v.x; sp.y += v.y; sp.z += v.z; sp.w += v.w;
            ts[t] = (v.x + v.y) + (v.z + v.w);
        }
        float4 spo;
        spo.x = sp.x * (1.f / TT); spo.y = sp.y * (1.f / TT);
        spo.z = sp.z * (1.f / TT); spo.w = sp.w * (1.f / TT);
        ((float4*)(sp_s + c_local * 32))[f4] = spo;
#pragma unroll
        for (int t = 0; t < TT; t++) {
            float s = ts[t];
            s += __shfl_down_sync(0xffffffffu, s, 4, 8);
            s += __shfl_down_sync(0xffffffffu, s, 2, 8);
            s += __shfl_down_sync(0xffffffffu, s, 1, 8);
            if (f4 == 0) tp_s[t * 64 + c_local] = s;   // [t][c]
        }
    }
    __syncthreads();

    // phase B: partial hidden over this split's 64 channels (no bias/relu yet)
    const int hw_l = tid & 31;
    const int rg   = tid >> 5;
    const int r0   = rg * 2, r1 = r0 + 1;
    float a0 = 0.f, a1 = 0.f;
#pragma unroll 8
    for (int cl = 0; cl < 64; cl++) {
        const float v = sp_s[cl * 32 + hw_l];
        a0 = fmaf(w1s[r0 * 64 + cl], v, a0);
        a1 = fmaf(w1s[r1 * 64 + cl], v, a1);
    }
    float* hp = g_hid_part + (size_t)(q * BB + b) * CR * HWN + tile * 32 + hw_l;
    hp[(size_t)r0 * HWN] = a0;
    hp[(size_t)r1 * HWN] = a1;

    // phase C: tp partials out, coalesced in c (layout [b][t][tile][c])
#pragma unroll
    for (int i = 0; i < 4; i++) {
        const int e  = tid + i * 256;       // 0..1023
        const int t  = e >> 6;
        const int cl = e & 63;
        g_tpp[(size_t)((b * TT + t) * 32 + tile) * CC + q * 64 + cl] = tp_s[t * 64 + cl];
    }
    // cp partials: sum over t
    if (tid < 64) {
        float s = 0.f;
#pragma unroll
        for (int t = 0; t < TT; t++) s += tp_s[t * 64 + tid];
        g_cpp[(size_t)(b * 32 + tile) * CC + q * 64 + tid] = s;
    }
}

// ---------------- K2: hid reduce + spatial att (+ cp reduce) -----------------
// grid = 264: blocks [0,256) att for (b, 32-hw window); blocks [256,264) cp.
__global__ void __launch_bounds__(256) att_kernel(const float* __restrict__ bs1,
                                                  const float* __restrict__ ws2,
                                                  const float* __restrict__ bs2) {
    const int tid = threadIdx.x;

    if (blockIdx.x < 256) {
        const int b   = blockIdx.x >> 5;
        const int hw0 = (blockIdx.x & 31) * 32;

        __shared__ float hid[CR * 32];   // [r][hw_l]
        __shared__ float w2s[CC * CR];   // 16KB

        for (int p = tid; p < CR * 32; p += 256) {
            const int r  = p >> 5;
            const int hw = p & 31;
            float s = bs1[r];
#pragma unroll
            for (int q = 0; q < 4; q++)
                s += g_hid_part[(size_t)((q * BB + b) * CR + r) * HWN + hw0 + hw];
            hid[r * 32 + hw] = fmaxf(s, 0.f);
        }
        for (int i = tid; i < CC * CR; i += 256) w2s[i] = ws2[i];
        __syncthreads();

        // warp per 32-channel slice; lane = hw -> coalesced 128B stores
        const int w    = tid >> 5;
        const int lane = tid & 31;
        float hv[CR];
#pragma unroll
        for (int r = 0; r < CR; r++) hv[r] = hid[r * 32 + lane];

        float* attb = g_att + (size_t)(b * CC) * HWN + hw0 + lane;
#pragma unroll 4
        for (int i = 0; i < 32; i++) {
            const int c = w * 32 + i;
            float a = bs2[c];
#pragma unroll
            for (int r = 0; r < CR; r++) a = fmaf(w2s[c * CR + r], hv[r], a);
            attb[(size_t)c * HWN] = sigmoidf(a);
        }
    } else {
        const int b = blockIdx.x - 256;
        float s = 0.f;
        for (int tile = 0; tile < 32; tile++)
            s += g_cpp[(size_t)(b * 32 + tile) * CC + tid];
        g_cp[b * CC + tid] = s * (1.f / (TT * HWN));
    }
}

// ---------------- K3: temporal + channel SE -> comb --------------------------
// one block per (b,t); 256 threads (== C)
__global__ void __launch_bounds__(256) small_se_kernel(
        const float* __restrict__ wt1, const float* __restrict__ bt1,
        const float* __restrict__ wt2, const float* __restrict__ bt2,
        const float* __restrict__ wc1, const float* __restrict__ bc1,
        const float* __restrict__ wc2, const float* __restrict__ bc2) {
    const int b   = blockIdx.x >> 4;
    const int t   = blockIdx.x & 15;
    const int tid = threadIdx.x;

    __shared__ float pt[CC], pc[CC], hids[2 * CR];

    // tp mean for (b, :, t): coalesced reduction over 32 tiles
    {
        float s = 0.f;
        const float* base = g_tpp + (size_t)(b * TT + t) * 32 * CC + tid;
#pragma unroll 8
        for (int tile = 0; tile < 32; tile++) s += base[tile * CC];
        pt[tid] = s * (1.f / HWN);
    }
    pc[tid] = g_cp[b * CC + tid];
    __syncthreads();

    if (tid < CR) {
        float s = bt1[tid];
        for (int c = 0; c < CC; c++) s = fmaf(wt1[tid * CC + c], pt[c], s);
        hids[tid] = fmaxf(s, 0.f);
    } else if (tid < 2 * CR) {
        const int r = tid - CR;
        float s = bc1[r];
        for (int c = 0; c < CC; c++) s = fmaf(wc1[r * CC + c], pc[c], s);
        hids[tid] = fmaxf(s, 0.f);
    }
    __syncthreads();

    float at = bt2[tid];
    float ac = bc2[tid];
#pragma unroll
    for (int r = 0; r < CR; r++) {
        at = fmaf(wt2[tid * CR + r], hids[r],      at);
        ac = fmaf(wc2[tid * CR + r], hids[CR + r], ac);
    }
    g_comb[(b * CC + tid) * TT + t] = sigmoidf(at) * sigmoidf(ac);
}

// ---------------- K4: pure streaming apply ----------------------------------
// one block per (b,c); 256 threads
__global__ void __launch_bounds__(256) apply_kernel(const float* __restrict__ x,
                                                    float* __restrict__ out) {
    const int bc  = blockIdx.x;
    const int tid = threadIdx.x;

    __shared__ float combs[TT];
    if (tid < TT) combs[tid] = g_comb[bc * TT + tid];

    const float4 a = ((const float4*)(g_att + (size_t)bc * HWN))[tid];
    __syncthreads();

    const float4* xp = (const float4*)(x + (size_t)bc * (TT * HWN));
    float4* op       = (float4*)(out + (size_t)bc * (TT * HWN));

#pragma unroll
    for (int t = 0; t < TT; t++) {
        const float s = combs[t];
        float4 v = xp[t * (HWN / 4) + tid];
        v.x = v.x * a.x * s;
        v.y = v.y * a.y * s;
        v.z = v.z * a.z * s;
        v.w = v.w * a.w * s;
        op[t * (HWN / 4) + tid] = v;
    }
}

// ---------------- launch -----------------------------------------------------
extern "C" void kernel_launch(void* const* d_in, const int* in_sizes, int n_in,
                              void* d_out, int out_size) {
    const float* x   = (const float*)d_in[0];
    const float* ws1 = (const float*)d_in[1];
    const float* bs1 = (const float*)d_in[2];
    const float* ws2 = (const float*)d_in[3];
    const float* bs2 = (const float*)d_in[4];
    const float* wt1 = (const float*)d_in[5];
    const float* bt1 = (const float*)d_in[6];
    const float* wt2 = (const float*)d_in[7];
    const float* bt2 = (const float*)d_in[8];
    const float* wc1 = (const float*)d_in[9];
    const float* bc1 = (const float*)d_in[10];
    const float* wc2 = (const float*)d_in[11];
    const float* bc2 = (const float*)d_in[12];
    float* out = (float*)d_out;

    pool_hid_kernel<<<BB * 32 * 4, 256>>>(x, ws1);
    att_kernel<<<264, 256>>>(bs1, ws2, bs2);
    small_se_kernel<<<BB * TT, 256>>>(wt1, bt1, wt2, bt2, wc1, bc1, wc2, bc2);
    apply_kernel<<<BB * CC, 256>>>(x, out);
}

// round 8
// speedup vs baseline: 1.0710x; 1.0710x over previous
#include <cuda_runtime.h>
#include <math.h>

#define BB 8
#define CC 256
#define TT 16
#define HWN 1024
#define CR 16
#define G 512   // persistent grid size; must be <= 148 * 4 (guaranteed resident)

// ---------------- scratch (device globals; no allocation) -------------------
__device__ float g_hid_part[4 * BB * CR * HWN];  // partial hidden [q][b][r][hw] (2MB)
__device__ float g_tpp[BB * TT * 32 * CC];       // tp partials [b][t][tile][c] (4MB)
__device__ float g_cpp[BB * 32 * CC];            // cp partials [b][tile][c] (256KB)
__device__ float g_comb[BB * CC * TT];           // temporal_att * channel_att
__device__ float g_att[BB * CC * HWN];           // spatial attention (8MB)
__device__ unsigned g_barcnt;                    // barrier arrival counter (self-resetting)
__device__ unsigned g_bargen;                    // barrier generation (monotonic)

__device__ __forceinline__ float sigmoidf(float a) {
    return 1.0f / (1.0f + __expf(-a));
}

// all-CTA barrier; safe because all G CTAs are guaranteed co-resident.
__device__ __forceinline__ void grid_barrier() {
    __syncthreads();
    if (threadIdx.x == 0) {
        volatile unsigned* genp = &g_bargen;
        const unsigned gen = *genp;          // read BEFORE arrival
        __threadfence();                     // publish this CTA's writes
        const unsigned a = atomicAdd(&g_barcnt, 1u);
        if (a == (unsigned)(G - 1)) {
            atomicExch(&g_barcnt, 0u);
            __threadfence();
            atomicAdd(&g_bargen, 1u);        // release
        } else {
            while (*genp == gen) { __nanosleep(64); }
        }
        __threadfence();                     // acquire
    }
    __syncthreads();
}

// ---------------- fused persistent kernel ------------------------------------
__global__ void __launch_bounds__(256, 4) fused_kernel(
        const float* __restrict__ x,
        const float* __restrict__ ws1, const float* __restrict__ bs1,
        const float* __restrict__ ws2, const float* __restrict__ bs2,
        const float* __restrict__ wt1, const float* __restrict__ bt1,
        const float* __restrict__ wt2, const float* __restrict__ bt2,
        const float* __restrict__ wc1, const float* __restrict__ bc1,
        const float* __restrict__ wc2, const float* __restrict__ bc2,
        float* __restrict__ out) {
    __shared__ float sm[4096];   // 16 KB, reused across phases
    const int tid = threadIdx.x;
    const int bid = blockIdx.x;

    // ================= Phase A: stream x -> hid partials + tp/cp partials ====
    {
        float* w1s  = sm;            // [r][c_local]   1024
        float* sp_s = sm + 1024;     // [c_local][hw]  2048
        float* tp_s = sm + 3072;     // [t][c_local]   1024

        for (int j = bid; j < 1024; j += G) {
            const int q    = j & 3;
            const int tile = (j >> 2) & 31;
            const int b    = j >> 7;

            for (int i = tid; i < CR * 64; i += 256)
                w1s[i] = ws1[(i >> 6) * CC + q * 64 + (i & 63)];

            const int f4  = tid & 7;
            const int cl2 = tid >> 3;
            const float4* xb = (const float4*)x;

#pragma unroll
            for (int i = 0; i < 2; i++) {
                const int c_local = cl2 + 32 * i;
                const int c = q * 64 + c_local;
                const size_t rowbase = (size_t)(b * CC + c) * TT * (HWN / 4) + tile * 8 + f4;
                float4 sp = make_float4(0.f, 0.f, 0.f, 0.f);
                float ts[TT];
#pragma unroll
                for (int t = 0; t < TT; t++) {
                    float4 v = xb[rowbase + t * (HWN / 4)];
                    sp.x += v.x; sp.y += v.y; sp.z += v.z; sp.w += v.w;
                    ts[t] = (v.x + v.y) + (v.z + v.w);
                }
                float4 spo;
                spo.x = sp.x * (1.f / TT); spo.y = sp.y * (1.f / TT);
                spo.z = sp.z * (1.f / TT); spo.w = sp.w * (1.f / TT);
                ((float4*)(sp_s + c_local * 32))[f4] = spo;
#pragma unroll
                for (int t = 0; t < TT; t++) {
                    float s = ts[t];
                    s += __shfl_down_sync(0xffffffffu, s, 4, 8);
                    s += __shfl_down_sync(0xffffffffu, s, 2, 8);
                    s += __shfl_down_sync(0xffffffffu, s, 1, 8);
                    if (f4 == 0) tp_s[t * 64 + c_local] = s;
                }
            }
            __syncthreads();

            // partial first-layer hidden over this split's 64 channels
            const int hw_l = tid & 31;
            const int rg   = tid >> 5;
            const int r0   = rg * 2, r1 = r0 + 1;
            float a0 = 0.f, a1 = 0.f;
#pragma unroll 8
            for (int cl = 0; cl < 64; cl++) {
                const float v = sp_s[cl * 32 + hw_l];
                a0 = fmaf(w1s[r0 * 64 + cl], v, a0);
                a1 = fmaf(w1s[r1 * 64 + cl], v, a1);
            }
            float* hp = g_hid_part + (size_t)(q * BB + b) * CR * HWN + tile * 32 + hw_l;
            hp[(size_t)r0 * HWN] = a0;
            hp[(size_t)r1 * HWN] = a1;

            // tp partials out (layout [b][t][tile][c], coalesced in c)
#pragma unroll
            for (int i = 0; i < 4; i++) {
                const int e  = tid + i * 256;
                const int t  = e >> 6;
                const int cl = e & 63;
                g_tpp[(size_t)((b * TT + t) * 32 + tile) * CC + q * 64 + cl] = tp_s[t * 64 + cl];
            }
            if (tid < 64) {
                float s = 0.f;
#pragma unroll
                for (int t = 0; t < TT; t++) s += tp_s[t * 64 + tid];
                g_cpp[(size_t)(b * 32 + tile) * CC + q * 64 + tid] = s;
            }
            __syncthreads();
        }
    }
    grid_barrier();

    // ================= Phase B: spatial att (bid<256) / small SE (256..383) ==
    if (bid < 256) {
        const int b   = bid >> 5;
        const int hw0 = (bid & 31) * 32;
        float* hid = sm;   // [r][hw] 512 floats

        for (int p = tid; p < CR * 32; p += 256) {
            const int r  = p >> 5;
            const int hw = p & 31;
            float s = bs1[r];
#pragma unroll
            for (int q = 0; q < 4; q++)
                s += __ldcg(&g_hid_part[(size_t)((q * BB + b) * CR + r) * HWN + hw0 + hw]);
            hid[p] = fmaxf(s, 0.f);
        }
        __syncthreads();

        const int w    = tid >> 5;
        const int lane = tid & 31;
        float hv[CR];
#pragma unroll
        for (int r = 0; r < CR; r++) hv[r] = hid[r * 32 + lane];

        float* attb = g_att + (size_t)(b * CC) * HWN + hw0 + lane;
#pragma unroll 4
        for (int i = 0; i < 32; i++) {
            const int c = w * 32 + i;
            const float4* wr = (const float4*)(ws2 + c * CR);
            const float4 w0 = wr[0], w1 = wr[1], w2 = wr[2], w3 = wr[3];
            float a = bs2[c];
            a = fmaf(w0.x, hv[0],  a); a = fmaf(w0.y, hv[1],  a);
            a = fmaf(w0.z, hv[2],  a); a = fmaf(w0.w, hv[3],  a);
            a = fmaf(w1.x, hv[4],  a); a = fmaf(w1.y, hv[5],  a);
            a = fmaf(w1.z, hv[6],  a); a = fmaf(w1.w, hv[7],  a);
            a = fmaf(w2.x, hv[8],  a); a = fmaf(w2.y, hv[9],  a);
            a = fmaf(w2.z, hv[10], a); a = fmaf(w2.w, hv[11], a);
            a = fmaf(w3.x, hv[12], a); a = fmaf(w3.y, hv[13], a);
            a = fmaf(w3.z, hv[14], a); a = fmaf(w3.w, hv[15], a);
            attb[(size_t)c * HWN] = sigmoidf(a);
        }
    } else if (bid < 384) {
        const int idx = bid - 256;
        const int b   = idx >> 4;
        const int t   = idx & 15;
        float* pt   = sm;         // [256]
        float* pc   = sm + 256;   // [256]
        float* hids = sm + 512;   // [32]

        {
            float s = 0.f;
            const float* base = g_tpp + (size_t)(b * TT + t) * 32 * CC + tid;
#pragma unroll 8
            for (int tile = 0; tile < 32; tile++) s += __ldcg(base + tile * CC);
            pt[tid] = s * (1.f / HWN);

            float s2 = 0.f;
            const float* base2 = g_cpp + (size_t)b * 32 * CC + tid;
#pragma unroll 8
            for (int tile = 0; tile < 32; tile++) s2 += __ldcg(base2 + tile * CC);
            pc[tid] = s2 * (1.f / (TT * HWN));
        }
        __syncthreads();

        if (tid < CR) {
            float s = bt1[tid];
            for (int c = 0; c < CC; c++) s = fmaf(wt1[tid * CC + c], pt[c], s);
            hids[tid] = fmaxf(s, 0.f);
        } else if (tid < 2 * CR) {
            const int r = tid - CR;
            float s = bc1[r];
            for (int c = 0; c < CC; c++) s = fmaf(wc1[r * CC + c], pc[c], s);
            hids[tid] = fmaxf(s, 0.f);
        }
        __syncthreads();

        float at = bt2[tid];
        float ac = bc2[tid];
#pragma unroll
        for (int r = 0; r < CR; r++) {
            at = fmaf(wt2[tid * CR + r], hids[r],      at);
            ac = fmaf(wc2[tid * CR + r], hids[CR + r], ac);
        }
        g_comb[(b * CC + tid) * TT + t] = sigmoidf(at) * sigmoidf(ac);
    }
    grid_barrier();

    // ================= Phase C: streaming apply (2048 jobs, 4 per CTA) =======
    {
        float* smc = sm;   // [16] comb for current job
        for (int j = bid; j < 2048; j += G) {
            if (tid < TT) smc[tid] = __ldcg(&g_comb[j * TT + tid]);
            __syncthreads();

            const float4 a = __ldcg(((const float4*)(g_att + (size_t)j * HWN)) + tid);
            const float4* xp = (const float4*)(x + (size_t)j * (TT * HWN));
            float4* op       = (float4*)(out + (size_t)j * (TT * HWN));
#pragma unroll
            for (int t = 0; t < TT; t++) {
                const float s = smc[t];
                float4 v = xp[t * (HWN / 4) + tid];
                v.x = v.x * a.x * s;
                v.y = v.y * a.y * s;
                v.z = v.z * a.z * s;
                v.w = v.w * a.w * s;
                op[t * (HWN / 4) + tid] = v;
            }
            __syncthreads();
        }
    }
}

// ---------------- launch -----------------------------------------------------
extern "C" void kernel_launch(void* const* d_in, const int* in_sizes, int n_in,
                              void* d_out, int out_size) {
    const float* x   = (const float*)d_in[0];
    const float* ws1 = (const float*)d_in[1];
    const float* bs1 = (const float*)d_in[2];
    const float* ws2 = (const float*)d_in[3];
    const float* bs2 = (const float*)d_in[4];
    const float* wt1 = (const float*)d_in[5];
    const float* bt1 = (const float*)d_in[6];
    const float* wt2 = (const float*)d_in[7];
    const float* bt2 = (const float*)d_in[8];
    const float* wc1 = (const float*)d_in[9];
    const float* bc1 = (const float*)d_in[10];
    const float* wc2 = (const float*)d_in[11];
    const float* bc2 = (const float*)d_in[12];
    float* out = (float*)d_out;

    fused_kernel<<<G, 256>>>(x, ws1, bs1, ws2, bs2,
                             wt1, bt1, wt2, bt2,
                             wc1, bc1, wc2, bc2, out);
}